// round 2
// baseline (speedup 1.0000x reference)
#include <cuda_runtime.h>
#include <cuda_bf16.h>

// VQ quantizer: z [N,64] f32, codebook [K,64] f32.
// Outputs (concatenated f32): q_ste [N*64], loss [1], ids [N] (as float).
// q_ste = fl(z + fl(q - z)) to mimic reference STE rounding.
// loss = 1.25 * mean((z - q)^2)  (both reference terms are numerically equal).

#define D        64
#define TPB      256
#define ROW_PAD  68   // pad codebook rows to 68 floats: kills bank conflicts in gather

__device__ double g_partial[4096];

__global__ __launch_bounds__(TPB) void vq_main(
    const float* __restrict__ z, const float* __restrict__ cb,
    int N, int K,
    float* __restrict__ q_out, float* __restrict__ ids_out)
{
    extern __shared__ float smem[];
    float* cbs = smem;                       // K * ROW_PAD floats
    float* c2  = smem + (size_t)K * ROW_PAD; // K floats

    const int tid = threadIdx.x;

    // Stage codebook into smem (float4 loads), padded rows.
    const float4* cb4 = (const float4*)cb;
    const int nvec = K * (D / 4);
    for (int idx = tid; idx < nvec; idx += TPB) {
        int k = idx >> 4;        // D/4 == 16
        int c = idx & 15;
        float4 v = cb4[idx];
        *(float4*)&cbs[k * ROW_PAD + c * 4] = v;
    }
    __syncthreads();

    // Per-code squared norms.
    for (int k = tid; k < K; k += TPB) {
        const float* r = &cbs[k * ROW_PAD];
        float s = 0.f;
        #pragma unroll
        for (int i = 0; i < D; i++) s += r[i] * r[i];
        c2[k] = s;
    }
    __syncthreads();

    const int row = blockIdx.x * TPB + tid;
    float lsum = 0.f;

    if (row < N) {
        // z row in registers.
        float4 zr[16];
        const float4* zp = (const float4*)(z + (size_t)row * D);
        #pragma unroll
        for (int i = 0; i < 16; i++) zr[i] = zp[i];

        float z2 = 0.f;
        #pragma unroll
        for (int i = 0; i < 16; i++)
            z2 += zr[i].x * zr[i].x + zr[i].y * zr[i].y
                + zr[i].z * zr[i].z + zr[i].w * zr[i].w;

        float best = 3.402823466e38f;
        int   bid  = 0;

        for (int k = 0; k < K; k++) {
            const float4* crow = (const float4*)&cbs[k * ROW_PAD];
            float a0 = 0.f, a1 = 0.f, a2 = 0.f, a3 = 0.f;  // 4-way ILP breaks RAW chain
            #pragma unroll
            for (int i = 0; i < 16; i++) {
                float4 cv = crow[i];
                a0 += zr[i].x * cv.x;
                a1 += zr[i].y * cv.y;
                a2 += zr[i].z * cv.z;
                a3 += zr[i].w * cv.w;
            }
            float dot = (a0 + a1) + (a2 + a3);
            float d   = (z2 - 2.0f * dot) + c2[k];   // same association as reference
            if (d < best) { best = d; bid = k; }     // strict < -> first-index ties
        }

        // Epilogue: gather q, write STE output, accumulate loss partial.
        const float4* crow = (const float4*)&cbs[bid * ROW_PAD];
        float4* qo = (float4*)(q_out + (size_t)row * D);
        #pragma unroll
        for (int i = 0; i < 16; i++) {
            float4 cv = crow[i];
            float4 zv = zr[i];
            float dx = zv.x - cv.x, dy = zv.y - cv.y;
            float dz = zv.z - cv.z, dw = zv.w - cv.w;
            lsum += dx * dx + dy * dy + dz * dz + dw * dw;
            float4 o;
            o.x = zv.x + (cv.x - zv.x);   // fl(z + fl(q - z)) like the reference STE
            o.y = zv.y + (cv.y - zv.y);
            o.z = zv.z + (cv.z - zv.z);
            o.w = zv.w + (cv.w - zv.w);
            qo[i] = o;
        }
        if (ids_out) ids_out[row] = (float)bid;
    }

    // Deterministic block reduction of loss partial -> g_partial[block].
    #pragma unroll
    for (int off = 16; off; off >>= 1)
        lsum += __shfl_down_sync(0xffffffffu, lsum, off);

    __shared__ double wp[TPB / 32];
    if ((tid & 31) == 0) wp[tid >> 5] = (double)lsum;
    __syncthreads();
    if (tid == 0) {
        double s = 0.0;
        #pragma unroll
        for (int w = 0; w < TPB / 32; w++) s += wp[w];
        g_partial[blockIdx.x] = s;
    }
}

__global__ void vq_finalize(int nblocks, double inv_total, float* loss_out)
{
    __shared__ double sp[256];
    const int tid = threadIdx.x;
    double s = 0.0;
    for (int i = tid; i < nblocks; i += 256) s += g_partial[i];
    sp[tid] = s;
    __syncthreads();
    for (int off = 128; off; off >>= 1) {
        if (tid < off) sp[tid] += sp[tid + off];
        __syncthreads();
    }
    if (tid == 0) {
        double mean = sp[0] * inv_total;
        loss_out[0] = (float)(mean + 0.25 * mean);
    }
}

extern "C" void kernel_launch(void* const* d_in, const int* in_sizes, int n_in,
                              void* d_out, int out_size)
{
    const float* z  = (const float*)d_in[0];
    const float* cb = (const float*)d_in[1];
    const int N = in_sizes[0] / D;
    const int K = in_sizes[1] / D;

    float* out = (float*)d_out;
    float* q_out    = out;
    float* loss_ptr = nullptr;
    float* ids_ptr  = nullptr;

    const long base = (long)N * D;
    if ((long)out_size >= base + 1 + N) {           // q, loss, ids
        loss_ptr = out + base;
        ids_ptr  = out + base + 1;
    } else if ((long)out_size == base + N) {        // q, ids
        ids_ptr  = out + base;
    } else if ((long)out_size == base + 1) {        // q, loss
        loss_ptr = out + base;
    }

    const size_t smem_bytes = ((size_t)K * ROW_PAD + K) * sizeof(float);
    cudaFuncSetAttribute(vq_main, cudaFuncAttributeMaxDynamicSharedMemorySize,
                         (int)smem_bytes);

    const int blocks = (N + TPB - 1) / TPB;
    vq_main<<<blocks, TPB, smem_bytes>>>(z, cb, N, K, q_out, ids_ptr);

    if (loss_ptr) {
        double inv_total = 1.0 / ((double)N * (double)D);
        vq_finalize<<<1, 256>>>(blocks, inv_total, loss_ptr);
    }
}

// round 3
// speedup vs baseline: 1.0220x; 1.0220x over previous
#include <cuda_runtime.h>
#include <cuda_bf16.h>

// VQ quantizer: z [N,64] f32, codebook [K,64] f32.
// Outputs (concatenated f32): q_ste [N*64], loss [1], ids [N] (as float).
// Inner product uses packed fma.rn.f32x2 (FFMA2): bit-identical to two scalar
// fma.rn ops, 2x FMA throughput on sm_103a. Accumulator pairing (a0,a1)/(a2,a3)
// reproduces round-1's exact rounding, so argmin results are unchanged.

#define D        64
#define TPB      256
#define ROW_PAD  68   // 272B rows: 16B-aligned, reduces gather-epilogue conflicts

#define FMA_F32X2(d, a, b, c) \
    asm("fma.rn.f32x2 %0, %1, %2, %3;" : "=l"(d) : "l"(a), "l"(b), "l"(c))

__device__ double g_partial[4096];

__global__ __launch_bounds__(TPB) void vq_main(
    const float* __restrict__ z, const float* __restrict__ cb,
    int N, int K,
    float* __restrict__ q_out, float* __restrict__ ids_out)
{
    extern __shared__ float smem[];
    float* cbs = smem;                       // K * ROW_PAD floats
    float* c2  = smem + (size_t)K * ROW_PAD; // K floats

    const int tid = threadIdx.x;

    // Stage codebook into smem (float4 loads), padded rows.
    const float4* cb4 = (const float4*)cb;
    const int nvec = K * (D / 4);
    for (int idx = tid; idx < nvec; idx += TPB) {
        int k = idx >> 4;        // D/4 == 16
        int c = idx & 15;
        float4 v = cb4[idx];
        *(float4*)&cbs[k * ROW_PAD + c * 4] = v;
    }
    __syncthreads();

    // Per-code squared norms.
    for (int k = tid; k < K; k += TPB) {
        const float* r = &cbs[k * ROW_PAD];
        float s = 0.f;
        #pragma unroll
        for (int i = 0; i < D; i++) s += r[i] * r[i];
        c2[k] = s;
    }
    __syncthreads();

    const int row = blockIdx.x * TPB + tid;
    float lsum = 0.f;

    if (row < N) {
        // z row in registers, viewed as 32 packed f32x2 (b64) values.
        float4 zr[16];
        const float4* zp = (const float4*)(z + (size_t)row * D);
        #pragma unroll
        for (int i = 0; i < 16; i++) zr[i] = zp[i];

        unsigned long long zb[32];
        #pragma unroll
        for (int i = 0; i < 16; i++) {
            const ulonglong2 v = *(const ulonglong2*)&zr[i];
            zb[2 * i]     = v.x;   // packs (x, y)
            zb[2 * i + 1] = v.y;   // packs (z, w)
        }

        float z2 = 0.f;
        #pragma unroll
        for (int i = 0; i < 16; i++)
            z2 += zr[i].x * zr[i].x + zr[i].y * zr[i].y
                + zr[i].z * zr[i].z + zr[i].w * zr[i].w;

        float best = 3.402823466e38f;
        int   bid  = 0;

        #pragma unroll 2
        for (int k = 0; k < K; k++) {
            const ulonglong2* crow = (const ulonglong2*)&cbs[k * ROW_PAD];
            unsigned long long acc01 = 0ull, acc23 = 0ull;  // (a0,a1), (a2,a3)
            #pragma unroll
            for (int i = 0; i < 16; i++) {
                ulonglong2 cv = crow[i];               // one LDS.128 (broadcast)
                FMA_F32X2(acc01, zb[2 * i],     cv.x, acc01);
                FMA_F32X2(acc23, zb[2 * i + 1], cv.y, acc23);
            }
            float2 p01 = *(float2*)&acc01;   // (a0, a1)
            float2 p23 = *(float2*)&acc23;   // (a2, a3)
            float dot = (p01.x + p01.y) + (p23.x + p23.y);  // same order as round 1
            float d   = (z2 - 2.0f * dot) + c2[k];
            if (d < best) { best = d; bid = k; }            // strict < -> first-index
        }

        // Epilogue: gather q, write STE output, accumulate loss partial.
        const float4* crow = (const float4*)&cbs[bid * ROW_PAD];
        float4* qo = (float4*)(q_out + (size_t)row * D);
        #pragma unroll
        for (int i = 0; i < 16; i++) {
            float4 cv = crow[i];
            float4 zv = zr[i];
            float dx = zv.x - cv.x, dy = zv.y - cv.y;
            float dz = zv.z - cv.z, dw = zv.w - cv.w;
            lsum += dx * dx + dy * dy + dz * dz + dw * dw;
            float4 o;
            o.x = zv.x + (cv.x - zv.x);   // fl(z + fl(q - z)) like the reference STE
            o.y = zv.y + (cv.y - zv.y);
            o.z = zv.z + (cv.z - zv.z);
            o.w = zv.w + (cv.w - zv.w);
            qo[i] = o;
        }
        if (ids_out) ids_out[row] = (float)bid;
    }

    // Deterministic block reduction of loss partial -> g_partial[block].
    #pragma unroll
    for (int off = 16; off; off >>= 1)
        lsum += __shfl_down_sync(0xffffffffu, lsum, off);

    __shared__ double wp[TPB / 32];
    if ((tid & 31) == 0) wp[tid >> 5] = (double)lsum;
    __syncthreads();
    if (tid == 0) {
        double s = 0.0;
        #pragma unroll
        for (int w = 0; w < TPB / 32; w++) s += wp[w];
        g_partial[blockIdx.x] = s;
    }
}

__global__ void vq_finalize(int nblocks, double inv_total, float* loss_out)
{
    __shared__ double sp[256];
    const int tid = threadIdx.x;
    double s = 0.0;
    for (int i = tid; i < nblocks; i += 256) s += g_partial[i];
    sp[tid] = s;
    __syncthreads();
    for (int off = 128; off; off >>= 1) {
        if (tid < off) sp[tid] += sp[tid + off];
        __syncthreads();
    }
    if (tid == 0) {
        double mean = sp[0] * inv_total;
        loss_out[0] = (float)(mean + 0.25 * mean);
    }
}

extern "C" void kernel_launch(void* const* d_in, const int* in_sizes, int n_in,
                              void* d_out, int out_size)
{
    const float* z  = (const float*)d_in[0];
    const float* cb = (const float*)d_in[1];
    const int N = in_sizes[0] / D;
    const int K = in_sizes[1] / D;

    float* out = (float*)d_out;
    float* q_out    = out;
    float* loss_ptr = nullptr;
    float* ids_ptr  = nullptr;

    const long base = (long)N * D;
    if ((long)out_size >= base + 1 + N) {           // q, loss, ids
        loss_ptr = out + base;
        ids_ptr  = out + base + 1;
    } else if ((long)out_size == base + N) {        // q, ids
        ids_ptr  = out + base;
    } else if ((long)out_size == base + 1) {        // q, loss
        loss_ptr = out + base;
    }

    const size_t smem_bytes = ((size_t)K * ROW_PAD + K) * sizeof(float);
    cudaFuncSetAttribute(vq_main, cudaFuncAttributeMaxDynamicSharedMemorySize,
                         (int)smem_bytes);

    const int blocks = (N + TPB - 1) / TPB;
    vq_main<<<blocks, TPB, smem_bytes>>>(z, cb, N, K, q_out, ids_ptr);

    if (loss_ptr) {
        double inv_total = 1.0 / ((double)N * (double)D);
        vq_finalize<<<1, 256>>>(blocks, inv_total, loss_ptr);
    }
}